// round 4
// baseline (speedup 1.0000x reference)
#include <cuda_runtime.h>
#include <cstdint>

#define NE_MAX 100000
#define EMB 64
#define NREL 32

// Scratch (allocation-free rule: device globals)
__device__ __align__(16) float g_s[NE_MAX * EMB];      // sum of e * x per head
__device__ __align__(16) float g_denom[NE_MAX];        // sum of e per head
__device__ __align__(16) float g_cnt[NE_MAX];          // out-degree (constant per launch)
__device__ __align__(16) float g_agg[NE_MAX * EMB];    // current agg
__device__ __align__(16) float g_q[NE_MAX * EMB];      // Q = agg @ q_w

static __device__ __forceinline__ unsigned long long pack2(float a, float b) {
    unsigned long long r;
    asm("mov.b64 %0, {%1,%2};" : "=l"(r) : "f"(a), "f"(b));
    return r;
}
static __device__ __forceinline__ void unpack2(unsigned long long v, float& a, float& b) {
    asm("mov.b64 {%0,%1}, %2;" : "=f"(a), "=f"(b) : "l"(v));
}
static __device__ __forceinline__ unsigned long long fma2(unsigned long long a,
                                                          unsigned long long b,
                                                          unsigned long long c) {
    unsigned long long d;
    asm("fma.rn.f32x2 %0, %1, %2, %3;" : "=l"(d) : "l"(a), "l"(b), "l"(c));
    return d;
}
static __device__ __forceinline__ float tanh_fast(float x) {
    float y;
    asm("tanh.approx.f32 %0, %1;" : "=f"(y) : "f"(x));
    return y;
}

// ---------------------------------------------------------------------------
// zero g_s + g_denom (per hop)
__global__ void zero_sd_kernel(int N) {
    int i = blockIdx.x * blockDim.x + threadIdx.x;
    int st = gridDim.x * blockDim.x;
    float4* s4 = (float4*)g_s;
    int n4 = N * EMB / 4;
    for (int k = i; k < n4; k += st) s4[k] = make_float4(0.f, 0.f, 0.f, 0.f);
    float4* d4 = (float4*)g_denom;
    int m4 = (N + 3) / 4;
    for (int k = i; k < m4; k += st) d4[k] = make_float4(0.f, 0.f, 0.f, 0.f);
}

__global__ void zero_cnt_kernel(int N) {
    int i = blockIdx.x * blockDim.x + threadIdx.x;
    int st = gridDim.x * blockDim.x;
    float4* c4 = (float4*)g_cnt;
    int n4 = (N + 3) / 4;
    for (int k = i; k < n4; k += st) c4[k] = make_float4(0.f, 0.f, 0.f, 0.f);
}

// out-degree of head (constant across hops)
__global__ void degree_kernel(const int* __restrict__ head, int E) {
    int i = blockIdx.x * blockDim.x + threadIdx.x;
    int st = gridDim.x * blockDim.x;
    for (; i < E; i += st) atomicAdd(&g_cnt[head[i]], 1.0f);
}

// ---------------------------------------------------------------------------
// dst[ent] = src[ent] @ W  (64x64), warp per entity, W register-resident.
__global__ void __launch_bounds__(256, 1) qproj_kernel(
    const float* __restrict__ src, float* __restrict__ dst,
    const float* __restrict__ W, int N) {
    __shared__ __align__(16) float sx[2][8][2 * EMB];
    int lane = threadIdx.x & 31, w = threadIdx.x >> 5;
    unsigned long long W2[EMB];
#pragma unroll
    for (int i = 0; i < EMB; i++) {
        float2 kv = *(const float2*)(W + i * EMB + 2 * lane);
        W2[i] = pack2(kv.x, kv.y);
    }
    int gw = blockIdx.x * 8 + w, nw = gridDim.x * 8;
    int buf = 0;
    for (int ent = gw; ent < N; ent += nw, buf ^= 1) {
        float2 v = *(const float2*)(src + (size_t)ent * EMB + 2 * lane);
        *(float4*)(&sx[buf][w][4 * lane]) = make_float4(v.x, v.x, v.y, v.y);
        __syncwarp();
        const unsigned long long* xd = (const unsigned long long*)sx[buf][w];
        unsigned long long ya = 0ull, yb = 0ull;
#pragma unroll
        for (int i = 0; i < EMB; i += 2) {
            ya = fma2(xd[i], W2[i], ya);
            yb = fma2(xd[i + 1], W2[i + 1], yb);
        }
        float y0a, y1a, y0b, y1b;
        unpack2(ya, y0a, y1a);
        unpack2(yb, y0b, y1b);
        *(float2*)(dst + (size_t)ent * EMB + 2 * lane) =
            make_float2(y0a + y0b, y1a + y1b);
    }
}

// ---------------------------------------------------------------------------
// Fused edge pass: x = rel*agg[tail]; y = tanh(x @ k_w); att = dot(Q[head], y);
// e = exp(att); scatter s[head] += e*x; denom[head] += e.
// Warp per edge, k_w register-resident, next-edge gathers software-prefetched.
__global__ void __launch_bounds__(256, 1) edge_kernel(
    const float* __restrict__ agg, const float* __restrict__ Qm,
    const float* __restrict__ kw, const float* __restrict__ edge_emb,
    const int* __restrict__ head, const int* __restrict__ tail,
    const int* __restrict__ etype, int E) {
    __shared__ __align__(16) float srel[NREL * EMB];
    __shared__ __align__(16) float sx[2][8][2 * EMB];
    int tid = threadIdx.x;
    for (int i = tid; i < NREL * EMB; i += 256) srel[i] = edge_emb[i];
    __syncthreads();
    int lane = tid & 31, w = tid >> 5;

    unsigned long long K2[EMB];
#pragma unroll
    for (int i = 0; i < EMB; i++) {
        float2 kv = *(const float2*)(kw + i * EMB + 2 * lane);
        K2[i] = pack2(kv.x, kv.y);
    }

    int gw = blockIdx.x * 8 + w, nw = gridDim.x * 8;
    int e = gw;
    int h = 0, ty = 0;
    float2 a2 = make_float2(0.f, 0.f), q2 = make_float2(0.f, 0.f);
    if (e < E) {
        h = head[e];
        int t = tail[e];
        ty = etype[e];
        a2 = *(const float2*)(agg + (size_t)t * EMB + 2 * lane);
        q2 = *(const float2*)(Qm + (size_t)h * EMB + 2 * lane);
    }
    int buf = 0;
    while (e < E) {
        int en = e + nw;
        float2 r2 = *(const float2*)(srel + ty * EMB + 2 * lane);
        float x0 = r2.x * a2.x, x1 = r2.y * a2.y;
        *(float4*)(&sx[buf][w][4 * lane]) = make_float4(x0, x0, x1, x1);

        // prefetch next edge's gathers (fly under the FMA loop)
        int hn = 0, tyn = 0;
        float2 a2n = make_float2(0.f, 0.f), q2n = make_float2(0.f, 0.f);
        if (en < E) {
            hn = head[en];
            int tn = tail[en];
            tyn = etype[en];
            a2n = *(const float2*)(agg + (size_t)tn * EMB + 2 * lane);
            q2n = *(const float2*)(Qm + (size_t)hn * EMB + 2 * lane);
        }
        __syncwarp();

        const unsigned long long* xd = (const unsigned long long*)sx[buf][w];
        unsigned long long ya = 0ull, yb = 0ull;
#pragma unroll
        for (int i = 0; i < EMB; i += 2) {
            ya = fma2(xd[i], K2[i], ya);
            yb = fma2(xd[i + 1], K2[i + 1], yb);
        }
        float y0a, y1a, y0b, y1b;
        unpack2(ya, y0a, y1a);
        unpack2(yb, y0b, y1b);
        float t0 = tanh_fast(y0a + y0b), t1 = tanh_fast(y1a + y1b);
        float p = q2.x * t0 + q2.y * t1;
#pragma unroll
        for (int o = 16; o; o >>= 1) p += __shfl_xor_sync(0xffffffffu, p, o);
        float ew = __expf(p);
        atomicAdd((float2*)(g_s + (size_t)h * EMB + 2 * lane),
                  make_float2(ew * x0, ew * x1));
        if (lane == 0) atomicAdd(&g_denom[h], ew);

        h = hn; ty = tyn; a2 = a2n; q2 = q2n; e = en; buf ^= 1;
    }
}

// ---------------------------------------------------------------------------
// agg = l2norm( (s/denom) / max(cnt,1) );  kg (+)= agg + entity_emb
__global__ void finalize_kernel(const float* __restrict__ ent_emb,
                                float* __restrict__ kg, int first, int N) {
    int lane = threadIdx.x & 31;
    int gw = (blockIdx.x * blockDim.x + threadIdx.x) >> 5;
    int nw = (gridDim.x * blockDim.x) >> 5;
    for (int ent = gw; ent < N; ent += nw) {
        float2 s2 = *(const float2*)(g_s + (size_t)ent * EMB + 2 * lane);
        float d = g_denom[ent];
        float c = fmaxf(g_cnt[ent], 1.0f);
        float inv = (d > 0.f) ? 1.0f / (d * c) : 0.0f;
        float a0 = s2.x * inv, a1 = s2.y * inv;
        float ss = a0 * a0 + a1 * a1;
#pragma unroll
        for (int o = 16; o; o >>= 1) ss += __shfl_xor_sync(0xffffffffu, ss, o);
        float sc = 1.0f / fmaxf(sqrtf(ss), 1e-12f);
        a0 *= sc; a1 *= sc;
        *(float2*)(g_agg + (size_t)ent * EMB + 2 * lane) = make_float2(a0, a1);
        float2 e2 = *(const float2*)(ent_emb + (size_t)ent * EMB + 2 * lane);
        float k0 = a0 + e2.x, k1 = a1 + e2.y;
        if (!first) {
            float2 kp = *(const float2*)(kg + (size_t)ent * EMB + 2 * lane);
            k0 += kp.x; k1 += kp.y;
        }
        *(float2*)(kg + (size_t)ent * EMB + 2 * lane) = make_float2(k0, k1);
    }
}

// ---------------------------------------------------------------------------
extern "C" void kernel_launch(void* const* d_in, const int* in_sizes, int n_in,
                              void* d_out, int out_size) {
    const float* ent      = (const float*)d_in[0];
    const float* edge_emb = (const float*)d_in[1];
    const float* qw       = (const float*)d_in[2];
    const float* kw       = (const float*)d_in[3];
    const int*   eidx     = (const int*)d_in[4];
    const int*   etype    = (const int*)d_in[5];
    int E = in_sizes[4] / 2;
    int N = in_sizes[0] / EMB;
    float* kg = (float*)d_out;
    const int* head = eidx;
    const int* tail = eidx + E;

    float* aggb = nullptr;
    cudaGetSymbolAddress((void**)&aggb, g_agg);
    float* qb = nullptr;
    cudaGetSymbolAddress((void**)&qb, g_q);

    const int TB = 256;
    const int G_EDGE = 304;   // persistent-ish, 1 block/SM (reg-heavy)
    const int G_PROJ = 304;
    const int G_LIGHT = 1024;

    // degree (constant across hops)
    zero_cnt_kernel<<<G_LIGHT, TB>>>(N);
    degree_kernel<<<G_LIGHT, TB>>>(head, E);

    // Q0 = entity_emb @ q_w
    qproj_kernel<<<G_PROJ, TB>>>(ent, qb, qw, N);

    // hop 0 (agg = entity_emb)
    zero_sd_kernel<<<G_LIGHT, TB>>>(N);
    edge_kernel<<<G_EDGE, TB>>>(ent, qb, kw, edge_emb, head, tail, etype, E);
    finalize_kernel<<<G_LIGHT, TB>>>(ent, kg, 1, N);

    // Q1 = agg @ q_w
    qproj_kernel<<<G_PROJ, TB>>>(aggb, qb, qw, N);

    // hop 1
    zero_sd_kernel<<<G_LIGHT, TB>>>(N);
    edge_kernel<<<G_EDGE, TB>>>(aggb, qb, kw, edge_emb, head, tail, etype, E);
    finalize_kernel<<<G_LIGHT, TB>>>(ent, kg, 0, N);
}

// round 8
// speedup vs baseline: 2.6354x; 2.6354x over previous
#include <cuda_runtime.h>
#include <cstdint>

#define NE_MAX 100000
#define EMB 64
#define NREL 32

// Scratch (allocation-free rule: device globals)
__device__ __align__(16) float g_s[NE_MAX * EMB];      // sum of e * x per head
__device__ __align__(16) float g_denom[NE_MAX];        // sum of e per head
__device__ __align__(16) float g_cnt[NE_MAX];          // out-degree (constant)
__device__ __align__(16) float g_agg[NE_MAX * EMB];    // current agg
__device__ __align__(16) float g_q[NE_MAX * EMB];      // Q = agg @ q_w

static __device__ __forceinline__ unsigned long long pack2(float a, float b) {
    unsigned long long r;
    asm("mov.b64 %0, {%1,%2};" : "=l"(r) : "f"(a), "f"(b));
    return r;
}
static __device__ __forceinline__ void unpack2(unsigned long long v, float& a, float& b) {
    asm("mov.b64 {%0,%1}, %2;" : "=f"(a), "=f"(b) : "l"(v));
}
static __device__ __forceinline__ unsigned long long fma2(unsigned long long a,
                                                          unsigned long long b,
                                                          unsigned long long c) {
    unsigned long long d;
    asm("fma.rn.f32x2 %0, %1, %2, %3;" : "=l"(d) : "l"(a), "l"(b), "l"(c));
    return d;
}
static __device__ __forceinline__ float tanh_fast(float x) {
    float y;
    asm("tanh.approx.f32 %0, %1;" : "=f"(y) : "f"(x));
    return y;
}

// ---------------------------------------------------------------------------
__global__ void zero_sd_kernel(int N) {
    int i = blockIdx.x * blockDim.x + threadIdx.x;
    int st = gridDim.x * blockDim.x;
    float4* s4 = (float4*)g_s;
    int n4 = N * EMB / 4;
    for (int k = i; k < n4; k += st) s4[k] = make_float4(0.f, 0.f, 0.f, 0.f);
    float4* d4 = (float4*)g_denom;
    int m4 = (N + 3) / 4;
    for (int k = i; k < m4; k += st) d4[k] = make_float4(0.f, 0.f, 0.f, 0.f);
}

__global__ void zero_cnt_kernel(int N) {
    int i = blockIdx.x * blockDim.x + threadIdx.x;
    int st = gridDim.x * blockDim.x;
    float4* c4 = (float4*)g_cnt;
    int n4 = (N + 3) / 4;
    for (int k = i; k < n4; k += st) c4[k] = make_float4(0.f, 0.f, 0.f, 0.f);
}

__global__ void degree_kernel(const int* __restrict__ head, int E) {
    int i = blockIdx.x * blockDim.x + threadIdx.x;
    int st = gridDim.x * blockDim.x;
    for (; i < E; i += st) atomicAdd(&g_cnt[head[i]], 1.0f);
}

// ---------------------------------------------------------------------------
// dst[ent] = src[ent] @ W  (64x64), warp per entity, W register-resident.
__global__ void __launch_bounds__(256, 1) qproj_kernel(
    const float* __restrict__ src, float* __restrict__ dst,
    const float* __restrict__ W, int N) {
    __shared__ __align__(16) float sx[8][2 * EMB];
    int lane = threadIdx.x & 31, w = threadIdx.x >> 5;
    unsigned long long W2[EMB];
#pragma unroll
    for (int i = 0; i < EMB; i++) {
        float2 kv = *(const float2*)(W + i * EMB + 2 * lane);
        W2[i] = pack2(kv.x, kv.y);
    }
    int gw = blockIdx.x * 8 + w, nw = gridDim.x * 8;
    for (int ent = gw; ent < N; ent += nw) {
        float2 v = *(const float2*)(src + (size_t)ent * EMB + 2 * lane);
        *(float4*)(&sx[w][4 * lane]) = make_float4(v.x, v.x, v.y, v.y);
        __syncwarp();
        const ulonglong2* xd = (const ulonglong2*)sx[w];
        unsigned long long ya = 0ull, yb = 0ull;
#pragma unroll
        for (int i = 0; i < 32; i++) {
            ulonglong2 xv = xd[i];
            ya = fma2(xv.x, W2[2 * i], ya);
            yb = fma2(xv.y, W2[2 * i + 1], yb);
        }
        float y0a, y1a, y0b, y1b;
        unpack2(ya, y0a, y1a);
        unpack2(yb, y0b, y1b);
        __syncwarp();
        *(float2*)(dst + (size_t)ent * EMB + 2 * lane) =
            make_float2(y0a + y0b, y1a + y1b);
    }
}

// ---------------------------------------------------------------------------
// Fused edge pass, 2 edges per warp-iteration, software pipeline depth 2:
// x = rel*agg[tail]; y = tanh(x @ k_w); att = dot(Q[head], y); e = exp(att);
// scatter s[head] += e*x; denom[head] += e.
__global__ void __launch_bounds__(256, 1) edge_kernel(
    const float* __restrict__ agg, const float* __restrict__ Qm,
    const float* __restrict__ kw, const float* __restrict__ edge_emb,
    const int* __restrict__ head, const int* __restrict__ tail,
    const int* __restrict__ etype, int E) {
    __shared__ __align__(16) float srel[NREL * EMB];
    __shared__ __align__(16) float sx[2][8][2][2 * EMB];  // buf, warp, edge, dup-x
    int tid = threadIdx.x;
    for (int i = tid; i < NREL * EMB; i += 256) srel[i] = edge_emb[i];
    __syncthreads();
    int lane = tid & 31, w = tid >> 5;

    unsigned long long K2[EMB];
#pragma unroll
    for (int i = 0; i < EMB; i++) {
        float2 kv = *(const float2*)(kw + i * EMB + 2 * lane);
        K2[i] = pack2(kv.x, kv.y);
    }

    int nwarp = gridDim.x * 8;
    int gw = blockIdx.x * 8 + w;
    int npair = (E + 1) >> 1;

    // pipeline state: indices cur (c), next (n); gathers for cur
    int p = gw;
    int hAc = 0, hBc = 0, tyAc = 0, tyBc = 0;
    bool vAc = false, vBc = false;
    float2 aAc = make_float2(0.f, 0.f), aBc = make_float2(0.f, 0.f);
    float2 qAc = make_float2(0.f, 0.f), qBc = make_float2(0.f, 0.f);
    int hAn = 0, hBn = 0, tyAn = 0, tyBn = 0, tAn = 0, tBn = 0;
    bool vAn = false, vBn = false;

    if (p < npair) {
        int e0 = 2 * p, e1 = 2 * p + 1;
        vAc = true;
        hAc = __ldg(head + e0);
        int t0 = __ldg(tail + e0);
        tyAc = __ldg(etype + e0);
        aAc = *(const float2*)(agg + (size_t)t0 * EMB + 2 * lane);
        qAc = *(const float2*)(Qm + (size_t)hAc * EMB + 2 * lane);
        if (e1 < E) {
            vBc = true;
            hBc = __ldg(head + e1);
            int t1 = __ldg(tail + e1);
            tyBc = __ldg(etype + e1);
            aBc = *(const float2*)(agg + (size_t)t1 * EMB + 2 * lane);
            qBc = *(const float2*)(Qm + (size_t)hBc * EMB + 2 * lane);
        }
        int pn = p + nwarp;
        if (pn < npair) {
            int f0 = 2 * pn, f1 = 2 * pn + 1;
            vAn = true;
            hAn = __ldg(head + f0);
            tAn = __ldg(tail + f0);
            tyAn = __ldg(etype + f0);
            if (f1 < E) {
                vBn = true;
                hBn = __ldg(head + f1);
                tBn = __ldg(tail + f1);
                tyBn = __ldg(etype + f1);
            }
        }
    }

    int buf = 0;
    while (p < npair) {
        // ---- compute x for current pair, stage to smem ----
        float2 rA = *(const float2*)(srel + tyAc * EMB + 2 * lane);
        float2 rB = *(const float2*)(srel + tyBc * EMB + 2 * lane);
        float xA0 = rA.x * aAc.x, xA1 = rA.y * aAc.y;
        float xB0 = rB.x * aBc.x, xB1 = rB.y * aBc.y;
        *(float4*)(&sx[buf][w][0][4 * lane]) = make_float4(xA0, xA0, xA1, xA1);
        *(float4*)(&sx[buf][w][1][4 * lane]) = make_float4(xB0, xB0, xB1, xB1);

        // ---- issue gathers for next pair (indices already resident) ----
        float2 aAn = make_float2(0.f, 0.f), aBn = make_float2(0.f, 0.f);
        float2 qAn = make_float2(0.f, 0.f), qBn = make_float2(0.f, 0.f);
        if (vAn) {
            aAn = *(const float2*)(agg + (size_t)tAn * EMB + 2 * lane);
            qAn = *(const float2*)(Qm + (size_t)hAn * EMB + 2 * lane);
        }
        if (vBn) {
            aBn = *(const float2*)(agg + (size_t)tBn * EMB + 2 * lane);
            qBn = *(const float2*)(Qm + (size_t)hBn * EMB + 2 * lane);
        }
        // ---- load indices for pair p+2 ----
        int hAn2 = 0, hBn2 = 0, tyAn2 = 0, tyBn2 = 0, tAn2 = 0, tBn2 = 0;
        bool vAn2 = false, vBn2 = false;
        int pn2 = p + 2 * nwarp;
        if (pn2 < npair) {
            int f0 = 2 * pn2, f1 = 2 * pn2 + 1;
            vAn2 = true;
            hAn2 = __ldg(head + f0);
            tAn2 = __ldg(tail + f0);
            tyAn2 = __ldg(etype + f0);
            if (f1 < E) {
                vBn2 = true;
                hBn2 = __ldg(head + f1);
                tBn2 = __ldg(tail + f1);
                tyBn2 = __ldg(etype + f1);
            }
        }
        __syncwarp();

        // ---- dual matvec: 4 independent f32x2 accumulator chains ----
        const ulonglong2* xdA = (const ulonglong2*)sx[buf][w][0];
        const ulonglong2* xdB = (const ulonglong2*)sx[buf][w][1];
        unsigned long long yAa = 0ull, yAb = 0ull, yBa = 0ull, yBb = 0ull;
#pragma unroll
        for (int i = 0; i < 32; i++) {
            ulonglong2 vA = xdA[i];
            ulonglong2 vB = xdB[i];
            yAa = fma2(vA.x, K2[2 * i], yAa);
            yAb = fma2(vA.y, K2[2 * i + 1], yAb);
            yBa = fma2(vB.x, K2[2 * i], yBa);
            yBb = fma2(vB.y, K2[2 * i + 1], yBb);
        }
        float a0, a1, b0, b1;
        unpack2(yAa, a0, a1);
        unpack2(yAb, b0, b1);
        float tA0 = tanh_fast(a0 + b0), tA1 = tanh_fast(a1 + b1);
        unpack2(yBa, a0, a1);
        unpack2(yBb, b0, b1);
        float tB0 = tanh_fast(a0 + b0), tB1 = tanh_fast(a1 + b1);
        float pA = qAc.x * tA0 + qAc.y * tA1;
        float pB = qBc.x * tB0 + qBc.y * tB1;
#pragma unroll
        for (int o = 16; o; o >>= 1) {
            pA += __shfl_xor_sync(0xffffffffu, pA, o);
            pB += __shfl_xor_sync(0xffffffffu, pB, o);
        }
        float ewA = __expf(pA), ewB = __expf(pB);

        if (vAc)
            atomicAdd((float2*)(g_s + (size_t)hAc * EMB + 2 * lane),
                      make_float2(ewA * xA0, ewA * xA1));
        if (vBc)
            atomicAdd((float2*)(g_s + (size_t)hBc * EMB + 2 * lane),
                      make_float2(ewB * xB0, ewB * xB1));
        if (lane == 0 && vAc) atomicAdd(&g_denom[hAc], ewA);
        if (lane == 1 && vBc) atomicAdd(&g_denom[hBc], ewB);

        // ---- rotate pipeline ----
        hAc = hAn; hBc = hBn; tyAc = tyAn; tyBc = tyBn;
        vAc = vAn; vBc = vBn;
        aAc = aAn; aBc = aBn; qAc = qAn; qBc = qBn;
        hAn = hAn2; hBn = hBn2; tyAn = tyAn2; tyBn = tyBn2;
        tAn = tAn2; tBn = tBn2; vAn = vAn2; vBn = vBn2;
        p += nwarp;
        buf ^= 1;
    }
}

// ---------------------------------------------------------------------------
// agg = l2norm( (s/denom) / max(cnt,1) );  kg (+)= agg + entity_emb
__global__ void finalize_kernel(const float* __restrict__ ent_emb,
                                float* __restrict__ kg, int first, int N) {
    int lane = threadIdx.x & 31;
    int gw = (blockIdx.x * blockDim.x + threadIdx.x) >> 5;
    int nw = (gridDim.x * blockDim.x) >> 5;
    for (int ent = gw; ent < N; ent += nw) {
        float2 s2 = *(const float2*)(g_s + (size_t)ent * EMB + 2 * lane);
        float d = g_denom[ent];
        float c = fmaxf(g_cnt[ent], 1.0f);
        float inv = (d > 0.f) ? 1.0f / (d * c) : 0.0f;
        float a0 = s2.x * inv, a1 = s2.y * inv;
        float ss = a0 * a0 + a1 * a1;
#pragma unroll
        for (int o = 16; o; o >>= 1) ss += __shfl_xor_sync(0xffffffffu, ss, o);
        float sc = 1.0f / fmaxf(sqrtf(ss), 1e-12f);
        a0 *= sc; a1 *= sc;
        *(float2*)(g_agg + (size_t)ent * EMB + 2 * lane) = make_float2(a0, a1);
        float2 e2 = *(const float2*)(ent_emb + (size_t)ent * EMB + 2 * lane);
        float k0 = a0 + e2.x, k1 = a1 + e2.y;
        if (!first) {
            float2 kp = *(const float2*)(kg + (size_t)ent * EMB + 2 * lane);
            k0 += kp.x; k1 += kp.y;
        }
        *(float2*)(kg + (size_t)ent * EMB + 2 * lane) = make_float2(k0, k1);
    }
}

// ---------------------------------------------------------------------------
extern "C" void kernel_launch(void* const* d_in, const int* in_sizes, int n_in,
                              void* d_out, int out_size) {
    const float* ent      = (const float*)d_in[0];
    const float* edge_emb = (const float*)d_in[1];
    const float* qw       = (const float*)d_in[2];
    const float* kw       = (const float*)d_in[3];
    const int*   eidx     = (const int*)d_in[4];
    const int*   etype    = (const int*)d_in[5];
    int E = in_sizes[4] / 2;
    int N = in_sizes[0] / EMB;
    float* kg = (float*)d_out;
    const int* head = eidx;
    const int* tail = eidx + E;

    float* aggb = nullptr;
    cudaGetSymbolAddress((void**)&aggb, g_agg);
    float* qb = nullptr;
    cudaGetSymbolAddress((void**)&qb, g_q);

    const int TB = 256;
    const int G_EDGE = 304;
    const int G_PROJ = 304;
    const int G_LIGHT = 1024;

    // degree (constant across hops)
    zero_cnt_kernel<<<G_LIGHT, TB>>>(N);
    degree_kernel<<<G_LIGHT, TB>>>(head, E);

    // Q0 = entity_emb @ q_w
    qproj_kernel<<<G_PROJ, TB>>>(ent, qb, qw, N);

    // hop 0 (agg = entity_emb)
    zero_sd_kernel<<<G_LIGHT, TB>>>(N);
    edge_kernel<<<G_EDGE, TB>>>(ent, qb, kw, edge_emb, head, tail, etype, E);
    finalize_kernel<<<G_LIGHT, TB>>>(ent, kg, 1, N);

    // Q1 = agg @ q_w
    qproj_kernel<<<G_PROJ, TB>>>(aggb, qb, qw, N);

    // hop 1
    zero_sd_kernel<<<G_LIGHT, TB>>>(N);
    edge_kernel<<<G_EDGE, TB>>>(aggb, qb, kw, edge_emb, head, tail, etype, E);
    finalize_kernel<<<G_LIGHT, TB>>>(ent, kg, 0, N);
}